// round 3
// baseline (speedup 1.0000x reference)
#include <cuda_runtime.h>
#include <cuda_bf16.h>
#include <cstdint>

// Problem constants
#define IDIM   80
#define HDIM   512
#define WIN    160      // IN_EXTRA + IDIM
#define NSHIFT 81       // IN_EXTRA + 1
#define NTOK   2048     // B*T
#define KSEL   128      // 2*CDIM
#define DOUT   160      // ODIM*OUT_EXTRA

// ---------------- scratch (__device__ globals; no allocation) ----------------
__device__ float g_C[WIN * WIN];        // Gram matrix W_enc^T W_enc  (160x160)
__device__ float g_v[WIN];              // W_enc^T b_enc
__device__ float g_energy[NTOK * NSHIFT];
__device__ int   g_hind[NTOK];

// ---------------- K1a: C = W^T W (tiled) ----------------
__global__ void gram_kernel(const float* __restrict__ W_enc) {
    __shared__ float SA[8][32];
    __shared__ float SB[8][32];
    int tid = threadIdx.x;
    int d0 = blockIdx.x * 32, e0 = blockIdx.y * 32;
    int dd = tid >> 5, ee = tid & 31;
    float a0 = 0.f, a1 = 0.f, a2 = 0.f, a3 = 0.f;
    for (int j0 = 0; j0 < HDIM; j0 += 8) {
        SA[tid >> 5][tid & 31] = W_enc[(j0 + (tid >> 5)) * WIN + d0 + (tid & 31)];
        SB[tid >> 5][tid & 31] = W_enc[(j0 + (tid >> 5)) * WIN + e0 + (tid & 31)];
        __syncthreads();
#pragma unroll
        for (int jj = 0; jj < 8; jj++) {
            float b = SB[jj][ee];
            a0 += SA[jj][dd] * b;
            a1 += SA[jj][dd + 8] * b;
            a2 += SA[jj][dd + 16] * b;
            a3 += SA[jj][dd + 24] * b;
        }
        __syncthreads();
    }
    g_C[(d0 + dd) * WIN + e0 + ee]      = a0;
    g_C[(d0 + dd + 8) * WIN + e0 + ee]  = a1;
    g_C[(d0 + dd + 16) * WIN + e0 + ee] = a2;
    g_C[(d0 + dd + 24) * WIN + e0 + ee] = a3;
}

// ---------------- K1b: v = W^T b ----------------
__global__ void vb_kernel(const float* __restrict__ W_enc, const float* __restrict__ b_enc) {
    int d = threadIdx.x;
    if (d < WIN) {
        float a = 0.f;
        for (int j = 0; j < HDIM; j++) a += b_enc[j] * W_enc[j * WIN + d];
        g_v[d] = a;
    }
}

// ---------------- K2: energies via Gram quadratic form ----------------
// E(t,s) = x^T C[q:q+80, q:q+80] x + 2 v[q:q+80].x   (const b^T b dropped: argmax-safe)
// grid (64, 11): blockIdx.x = token-group of 32, blockIdx.y = s-group of 8.
// warp lanes = 32 tokens (C reads warp-uniform -> smem broadcast), warp w -> shifts s0+w, s0+w+4.
#define NS 8
#define CROWS 87          // (NS-1) + 80
#define CPITCH 96         // 4 leading zero cols + 87 data + pad; mult of 4; covers max col idx 91
__global__ __launch_bounds__(128) void energy_kernel(const float* __restrict__ x) {
    __shared__ __align__(16) float Cs[CROWS * CPITCH];
    __shared__ float xs[32 * 81];
    __shared__ float vs[WIN];

    int tid = threadIdx.x;
    int lane = tid & 31;
    int w = tid >> 5;
    int tb = blockIdx.x * 32;
    int s0 = blockIdx.y * NS;
    int qlo = 73 - s0; if (qlo < 0) qlo = 0;

    // zero everything (incl. padding cols -> garbage*0 stays finite)
    for (int i = tid; i < CROWS * CPITCH; i += 128) Cs[i] = 0.f;
    for (int i = tid; i < 32 * 81; i += 128) xs[i] = 0.f;
    __syncthreads();
    for (int i = tid; i < CROWS * CROWS; i += 128) {
        int r = i / CROWS, c = i - r * CROWS;
        Cs[r * CPITCH + 4 + c] = g_C[(qlo + r) * WIN + qlo + c];
    }
    for (int i = tid; i < 32 * IDIM; i += 128) {
        int tok = i / IDIM, ii = i - tok * IDIM;
        xs[tok * 81 + ii] = x[(tb + tok) * IDIM + ii];
    }
    for (int i = tid; i < WIN; i += 128) vs[i] = g_v[i];
    __syncthreads();

    const float* myx = &xs[lane * 81];
    float xr[84];

#pragma unroll
    for (int si = 0; si < 2; si++) {
        int s = s0 + w + si * 4;
        if (s > 80) continue;
        int q = 80 - s;
        int coff = q - qlo;           // 0..7
        int p = coff & 3;
        int cbase = 4 + coff - p;     // aligned mod 4, >= 4

        // register-resident x, pre-shifted by p so C reads stay float4-aligned
#pragma unroll
        for (int k = 0; k < 84; k++) {
            int i2 = k - p;
            xr[k] = (i2 >= 0 && i2 < IDIM) ? myx[i2] : 0.f;
        }

        float acc = 0.f;
        for (int i = 0; i < IDIM; i++) {
            const float4* cr = reinterpret_cast<const float4*>(&Cs[(coff + i) * CPITCH + cbase]);
            float rd0 = 0.f, rd1 = 0.f;
#pragma unroll
            for (int k4 = 0; k4 < 21; k4++) {
                float4 f = cr[k4];
                if (k4 & 1) {
                    rd1 += f.x * xr[4 * k4] + f.y * xr[4 * k4 + 1]
                         + f.z * xr[4 * k4 + 2] + f.w * xr[4 * k4 + 3];
                } else {
                    rd0 += f.x * xr[4 * k4] + f.y * xr[4 * k4 + 1]
                         + f.z * xr[4 * k4 + 2] + f.w * xr[4 * k4 + 3];
                }
            }
            acc += myx[i] * (rd0 + rd1);
        }
        float cross = 0.f;
        for (int i = 0; i < IDIM; i++) cross += myx[i] * vs[q + i];
        g_energy[(tb + lane) * NSHIFT + s] = acc + 2.f * cross;
    }
}

// ---------------- K3: argmax over shifts (tie -> lowest s, matching jnp.argmax) ----
__global__ void argmax_kernel() {
    int t = blockIdx.x * (blockDim.x >> 5) + (threadIdx.x >> 5);
    int lane = threadIdx.x & 31;
    if (t >= NTOK) return;
    const float* e = g_energy + t * NSHIFT;
    float bv = -1e30f; int bi = 0x7fffffff;
    for (int s = lane; s < NSHIFT; s += 32) {
        float vv = e[s];
        if (vv > bv || (vv == bv && s < bi)) { bv = vv; bi = s; }
    }
#pragma unroll
    for (int o = 16; o; o >>= 1) {
        float ov = __shfl_down_sync(0xffffffffu, bv, o);
        int oi = __shfl_down_sync(0xffffffffu, bi, o);
        if (ov > bv || (ov == bv && oi < bi)) { bv = ov; bi = oi; }
    }
    if (lane == 0) g_hind[t] = bi;
}

// ---------------- K4: winning h -> mask_prev -> exact top-128 -> decoder window ----
__global__ __launch_bounds__(256) void select_decode_kernel(
    const float* __restrict__ x, const float* __restrict__ W_enc,
    const float* __restrict__ b_enc, const float* __restrict__ W_dec,
    const float* __restrict__ b_dec, const int* __restrict__ mask_prev,
    float* __restrict__ out)
{
    __shared__ float xs[IDIM];
    __shared__ float hs[HDIM];
    __shared__ float hk[HDIM];
    __shared__ unsigned long long keys[HDIM];
    __shared__ int qsh;

    int t = blockIdx.x;
    int tid = threadIdx.x, lane = tid & 31, w = tid >> 5;

    if (tid < IDIM) xs[tid] = x[t * IDIM + tid];
    if (tid == 0) qsh = 80 - g_hind[t];
    __syncthreads();
    int q = qsh;

    // h rows, warp-cooperative (coalesced W_enc reads)
    for (int j = w * 64; j < w * 64 + 64; j++) {
        const float* row = W_enc + j * WIN + q;
        float pa = row[lane] * xs[lane] + row[lane + 32] * xs[lane + 32];
        if (lane < 16) pa += row[lane + 64] * xs[lane + 64];
#pragma unroll
        for (int o = 16; o; o >>= 1) pa += __shfl_down_sync(0xffffffffu, pa, o);
        if (lane == 0) {
            float h = pa + b_enc[j];
            if (mask_prev[t * HDIM + j] != 0) h = 0.f;
            hs[j] = h;
            unsigned key = __float_as_uint(h * h);  // >=0 -> bit-monotonic
            keys[j] = ((unsigned long long)key << 32) | (unsigned)(511 - j); // desc val, asc idx
        }
    }
    __syncthreads();

    // bitonic sort, descending (top-128 lands first) — exact lax.top_k tie order
    for (int k = 2; k <= HDIM; k <<= 1) {
        for (int jj = k >> 1; jj > 0; jj >>= 1) {
            for (int idx = tid; idx < HDIM; idx += 256) {
                int ixj = idx ^ jj;
                if (ixj > idx) {
                    unsigned long long a = keys[idx], b2 = keys[ixj];
                    bool descBlk = ((idx & k) == 0);
                    bool sw = descBlk ? (a < b2) : (a > b2);
                    if (sw) { keys[idx] = b2; keys[ixj] = a; }
                }
            }
            __syncthreads();
        }
    }

    for (int i = tid; i < HDIM; i += 256) hk[i] = 0.f;
    __syncthreads();
    if (tid < KSEL) {
        int j = 511 - (int)(keys[tid] & 0xFFFFFFFFull);
        hk[j] = hs[j];
    }
    __syncthreads();

    // decoder: only the 80 rows [q, q+80) are ever gathered by the reference
    for (int r = 0; r < 10; r++) {
        int i = w * 10 + r;
        int o = q + i;
        const float* row = W_dec + o * HDIM;
        float acc = 0.f;
#pragma unroll
        for (int kk = 0; kk < 16; kk++) acc += row[lane + 32 * kk] * hk[lane + 32 * kk];
#pragma unroll
        for (int off = 16; off; off >>= 1) acc += __shfl_down_sync(0xffffffffu, acc, off);
        if (lane == 0) out[t * IDIM + i] = acc + b_dec[o];
    }
}

// ---------------- launch ----------------
extern "C" void kernel_launch(void* const* d_in, const int* in_sizes, int n_in,
                              void* d_out, int out_size) {
    const float* x        = (const float*)d_in[0];
    const float* W_enc    = (const float*)d_in[1];
    const float* b_enc    = (const float*)d_in[2];
    const float* W_dec    = (const float*)d_in[3];
    const float* b_dec    = (const float*)d_in[4];
    const int*   mask_prev= (const int*)d_in[5];
    float* out = (float*)d_out;

    gram_kernel<<<dim3(5, 5), 256>>>(W_enc);
    vb_kernel<<<1, 160>>>(W_enc, b_enc);
    energy_kernel<<<dim3(64, 11), 128>>>(x);
    argmax_kernel<<<NTOK / 8, 256>>>();
    select_decode_kernel<<<NTOK, 256>>>(x, W_enc, b_enc, W_dec, b_dec, mask_prev, out);
}

// round 4
// speedup vs baseline: 1.2370x; 1.2370x over previous
#include <cuda_runtime.h>
#include <cuda_bf16.h>
#include <cstdint>

// Problem constants
#define IDIM   80
#define HDIM   512
#define WIN    160      // IN_EXTRA + IDIM
#define NSHIFT 81       // IN_EXTRA + 1
#define NTOK   2048     // B*T
#define KSEL   128      // 2*CDIM
#define TPB    8        // tokens per hcompute block

// ---------------- scratch (__device__ globals; no allocation) ----------------
__device__ float g_C[WIN * WIN];          // Gram matrix W_enc^T W_enc  (160x160)
__device__ float g_v[WIN];                // W_enc^T b_enc
__device__ float g_energy[NTOK * NSHIFT];
__device__ int   g_hind[NTOK];
__device__ float g_WeT[WIN * HDIM];       // W_enc transposed: [i][j] = W_enc[j][i]
__device__ float g_WdT[HDIM * WIN];       // W_dec transposed: [j][o] = W_dec[o][j]
__device__ float g_h[NTOK * HDIM];        // masked h per token
__device__ unsigned long long g_keys[NTOK * HDIM];  // sort keys per token

// ---------------- K0: transposes (dims are multiples of 32) ----------------
__global__ void transpose_we_kernel(const float* __restrict__ W_enc) {
    __shared__ float tile[32][33];
    int bx = blockIdx.x * 32;   // col of W_enc (0..160)
    int by = blockIdx.y * 32;   // row of W_enc (0..512)
    int tx = threadIdx.x, ty = threadIdx.y;   // (32, 8)
#pragma unroll
    for (int r = 0; r < 4; r++)
        tile[ty + 8 * r][tx] = W_enc[(by + ty + 8 * r) * WIN + bx + tx];
    __syncthreads();
#pragma unroll
    for (int r = 0; r < 4; r++)
        g_WeT[(bx + ty + 8 * r) * HDIM + by + tx] = tile[tx][ty + 8 * r];
}

__global__ void transpose_wd_kernel(const float* __restrict__ W_dec) {
    __shared__ float tile[32][33];
    int bx = blockIdx.x * 32;   // col of W_dec (0..512)
    int by = blockIdx.y * 32;   // row of W_dec (0..160)
    int tx = threadIdx.x, ty = threadIdx.y;
#pragma unroll
    for (int r = 0; r < 4; r++)
        tile[ty + 8 * r][tx] = W_dec[(by + ty + 8 * r) * HDIM + bx + tx];
    __syncthreads();
#pragma unroll
    for (int r = 0; r < 4; r++)
        g_WdT[(bx + ty + 8 * r) * WIN + by + tx] = tile[tx][ty + 8 * r];
}

// ---------------- K1a: C = W^T W (tiled) ----------------
__global__ void gram_kernel(const float* __restrict__ W_enc) {
    __shared__ float SA[8][32];
    __shared__ float SB[8][32];
    int tid = threadIdx.x;
    int d0 = blockIdx.x * 32, e0 = blockIdx.y * 32;
    int dd = tid >> 5, ee = tid & 31;
    float a0 = 0.f, a1 = 0.f, a2 = 0.f, a3 = 0.f;
    for (int j0 = 0; j0 < HDIM; j0 += 8) {
        SA[tid >> 5][tid & 31] = W_enc[(j0 + (tid >> 5)) * WIN + d0 + (tid & 31)];
        SB[tid >> 5][tid & 31] = W_enc[(j0 + (tid >> 5)) * WIN + e0 + (tid & 31)];
        __syncthreads();
#pragma unroll
        for (int jj = 0; jj < 8; jj++) {
            float b = SB[jj][ee];
            a0 += SA[jj][dd] * b;
            a1 += SA[jj][dd + 8] * b;
            a2 += SA[jj][dd + 16] * b;
            a3 += SA[jj][dd + 24] * b;
        }
        __syncthreads();
    }
    g_C[(d0 + dd) * WIN + e0 + ee]      = a0;
    g_C[(d0 + dd + 8) * WIN + e0 + ee]  = a1;
    g_C[(d0 + dd + 16) * WIN + e0 + ee] = a2;
    g_C[(d0 + dd + 24) * WIN + e0 + ee] = a3;
}

// ---------------- K1b: v = W^T b (coalesced via WeT) ----------------
__global__ void vb_kernel(const float* __restrict__ b_enc) {
    __shared__ float red[256];
    int d = blockIdx.x;
    int tid = threadIdx.x;
    float a = b_enc[tid] * g_WeT[d * HDIM + tid]
            + b_enc[tid + 256] * g_WeT[d * HDIM + tid + 256];
    red[tid] = a;
    __syncthreads();
    for (int o = 128; o > 0; o >>= 1) {
        if (tid < o) red[tid] += red[tid + o];
        __syncthreads();
    }
    if (tid == 0) g_v[d] = red[0];
}

// ---------------- K2: energies via Gram quadratic form ----------------
// E(t,s) = x^T C[q:q+80, q:q+80] x + 2 v[q:q+80].x   (const b^T b dropped: argmax-safe)
#define NS 8
#define CROWS 87
#define CPITCH 96
__global__ __launch_bounds__(128) void energy_kernel(const float* __restrict__ x) {
    __shared__ __align__(16) float Cs[CROWS * CPITCH];
    __shared__ float xs[32 * 81];
    __shared__ float vs[WIN];

    int tid = threadIdx.x;
    int lane = tid & 31;
    int w = tid >> 5;
    int tb = blockIdx.x * 32;
    int s0 = blockIdx.y * NS;
    int qlo = 73 - s0; if (qlo < 0) qlo = 0;

    for (int i = tid; i < CROWS * CPITCH; i += 128) Cs[i] = 0.f;
    for (int i = tid; i < 32 * 81; i += 128) xs[i] = 0.f;
    __syncthreads();
    for (int i = tid; i < CROWS * CROWS; i += 128) {
        int r = i / CROWS, c = i - r * CROWS;
        Cs[r * CPITCH + 4 + c] = g_C[(qlo + r) * WIN + qlo + c];
    }
    for (int i = tid; i < 32 * IDIM; i += 128) {
        int tok = i / IDIM, ii = i - tok * IDIM;
        xs[tok * 81 + ii] = x[(tb + tok) * IDIM + ii];
    }
    for (int i = tid; i < WIN; i += 128) vs[i] = g_v[i];
    __syncthreads();

    const float* myx = &xs[lane * 81];
    float xr[84];

#pragma unroll
    for (int si = 0; si < 2; si++) {
        int s = s0 + w + si * 4;
        if (s > 80) continue;
        int q = 80 - s;
        int coff = q - qlo;           // 0..7
        int p = coff & 3;
        int cbase = 4 + coff - p;     // aligned mod 4

#pragma unroll
        for (int k = 0; k < 84; k++) {
            int i2 = k - p;
            xr[k] = (i2 >= 0 && i2 < IDIM) ? myx[i2] : 0.f;
        }

        float acc = 0.f;
        for (int i = 0; i < IDIM; i++) {
            const float4* cr = reinterpret_cast<const float4*>(&Cs[(coff + i) * CPITCH + cbase]);
            float rd0 = 0.f, rd1 = 0.f;
#pragma unroll
            for (int k4 = 0; k4 < 21; k4++) {
                float4 f = cr[k4];
                if (k4 & 1) {
                    rd1 += f.x * xr[4 * k4] + f.y * xr[4 * k4 + 1]
                         + f.z * xr[4 * k4 + 2] + f.w * xr[4 * k4 + 3];
                } else {
                    rd0 += f.x * xr[4 * k4] + f.y * xr[4 * k4 + 1]
                         + f.z * xr[4 * k4 + 2] + f.w * xr[4 * k4 + 3];
                }
            }
            acc += myx[i] * (rd0 + rd1);
        }
        float cross = 0.f;
        for (int i = 0; i < IDIM; i++) cross += myx[i] * vs[q + i];
        g_energy[(tb + lane) * NSHIFT + s] = acc + 2.f * cross;
    }
}

// ---------------- K3: argmax over shifts (tie -> lowest s) ----------------
__global__ void argmax_kernel() {
    int t = blockIdx.x * (blockDim.x >> 5) + (threadIdx.x >> 5);
    int lane = threadIdx.x & 31;
    if (t >= NTOK) return;
    const float* e = g_energy + t * NSHIFT;
    float bv = -1e30f; int bi = 0x7fffffff;
    for (int s = lane; s < NSHIFT; s += 32) {
        float vv = e[s];
        if (vv > bv || (vv == bv && s < bi)) { bv = vv; bi = s; }
    }
#pragma unroll
    for (int o = 16; o; o >>= 1) {
        float ov = __shfl_down_sync(0xffffffffu, bv, o);
        int oi = __shfl_down_sync(0xffffffffu, bi, o);
        if (ov > bv || (ov == bv && oi < bi)) { bv = ov; bi = oi; }
    }
    if (lane == 0) g_hind[t] = bi;
}

// ---------------- K4a: h for winning shift, 8 tokens/block, coalesced WeT ----
// xsp[t][i] = x_t[i - q_t] (zero outside window) -> no per-row predicates.
__global__ __launch_bounds__(256) void hcompute_kernel(
    const float* __restrict__ x, const float* __restrict__ b_enc,
    const int* __restrict__ mask_prev)
{
    __shared__ float xsp[TPB][WIN];
    __shared__ int qs[TPB];
    int tid = threadIdx.x;
    int tb = blockIdx.x * TPB;

    if (tid < TPB) qs[tid] = 80 - g_hind[tb + tid];
    for (int i = tid; i < TPB * WIN; i += 256) ((float*)xsp)[i] = 0.f;
    __syncthreads();
    for (int idx = tid; idx < TPB * IDIM; idx += 256) {
        int t = idx / IDIM, a = idx - t * IDIM;
        xsp[t][qs[t] + a] = x[(tb + t) * IDIM + a];
    }
    __syncthreads();

    int j0 = 2 * tid;
    float a0[TPB], a1[TPB];
#pragma unroll
    for (int t = 0; t < TPB; t++) { a0[t] = 0.f; a1[t] = 0.f; }

    for (int i = 0; i < WIN; i++) {
        float2 c = *reinterpret_cast<const float2*>(&g_WeT[i * HDIM + j0]);
#pragma unroll
        for (int t = 0; t < TPB; t++) {
            float xv = xsp[t][i];
            a0[t] += xv * c.x;
            a1[t] += xv * c.y;
        }
    }

    float bb0 = b_enc[j0], bb1 = b_enc[j0 + 1];
#pragma unroll
    for (int t = 0; t < TPB; t++) {
        int tg = tb + t;
        int2 m = *reinterpret_cast<const int2*>(&mask_prev[tg * HDIM + j0]);
        float h0 = a0[t] + bb0; if (m.x != 0) h0 = 0.f;
        float h1 = a1[t] + bb1; if (m.y != 0) h1 = 0.f;
        *reinterpret_cast<float2*>(&g_h[tg * HDIM + j0]) = make_float2(h0, h1);
        unsigned k0 = __float_as_uint(h0 * h0);
        unsigned k1 = __float_as_uint(h1 * h1);
        g_keys[tg * HDIM + j0]     = ((unsigned long long)k0 << 32) | (unsigned)(511 - j0);
        g_keys[tg * HDIM + j0 + 1] = ((unsigned long long)k1 << 32) | (unsigned)(511 - (j0 + 1));
    }
}

// ---------------- K4b: exact top-128 (bitonic) + sparse decoder window ----------------
__global__ __launch_bounds__(256) void sortdecode_kernel(
    const float* __restrict__ b_dec, float* __restrict__ out)
{
    __shared__ unsigned long long keys[HDIM];
    __shared__ float hs[HDIM];
    __shared__ float selv[KSEL];
    __shared__ int   selj[KSEL];
    __shared__ float psum[240];

    int t = blockIdx.x;
    int tid = threadIdx.x;
    int q = 80 - g_hind[t];

    keys[tid]       = g_keys[t * HDIM + tid];
    keys[tid + 256] = g_keys[t * HDIM + tid + 256];
    hs[tid]         = g_h[t * HDIM + tid];
    hs[tid + 256]   = g_h[t * HDIM + tid + 256];
    __syncthreads();

    // bitonic sort descending on (bits(h^2), 511-j): exact lax.top_k tie order
    for (int k = 2; k <= HDIM; k <<= 1) {
        for (int jj = k >> 1; jj > 0; jj >>= 1) {
            for (int idx = tid; idx < HDIM; idx += 256) {
                int ixj = idx ^ jj;
                if (ixj > idx) {
                    unsigned long long a = keys[idx], b2 = keys[ixj];
                    bool descBlk = ((idx & k) == 0);
                    bool sw = descBlk ? (a < b2) : (a > b2);
                    if (sw) { keys[idx] = b2; keys[ixj] = a; }
                }
            }
            __syncthreads();
        }
    }

    if (tid < KSEL) {
        int j = 511 - (int)(keys[tid] & 0xFFFFFFFFull);
        selj[tid] = j;
        selv[tid] = hs[j];
    }
    __syncthreads();

    // sparse decoder: out_i = sum_k selv[k] * WdT[selj[k]][q+i], k split into 3 groups
    if (tid < 240) {
        int g = tid / IDIM;       // 0..2
        int i = tid - g * IDIM;   // 0..79
        int k0 = (g == 0) ? 0 : (g == 1 ? 43 : 86);
        int k1 = (g == 0) ? 43 : (g == 1 ? 86 : KSEL);
        float a = 0.f;
        for (int k = k0; k < k1; k++)
            a += selv[k] * g_WdT[selj[k] * WIN + q + i];
        psum[tid] = a;
    }
    __syncthreads();
    if (tid < IDIM)
        out[t * IDIM + tid] = psum[tid] + psum[IDIM + tid] + psum[2 * IDIM + tid]
                            + b_dec[q + tid];
}

// ---------------- launch ----------------
extern "C" void kernel_launch(void* const* d_in, const int* in_sizes, int n_in,
                              void* d_out, int out_size) {
    const float* x        = (const float*)d_in[0];
    const float* W_enc    = (const float*)d_in[1];
    const float* b_enc    = (const float*)d_in[2];
    const float* W_dec    = (const float*)d_in[3];
    const float* b_dec    = (const float*)d_in[4];
    const int*   mask_prev= (const int*)d_in[5];
    float* out = (float*)d_out;

    transpose_we_kernel<<<dim3(5, 16), dim3(32, 8)>>>(W_enc);
    transpose_wd_kernel<<<dim3(16, 5), dim3(32, 8)>>>(W_dec);
    gram_kernel<<<dim3(5, 5), 256>>>(W_enc);
    vb_kernel<<<WIN, 256>>>(b_enc);
    energy_kernel<<<dim3(64, 11), 128>>>(x);
    argmax_kernel<<<NTOK / 8, 256>>>();
    hcompute_kernel<<<NTOK / TPB, 256>>>(x, b_enc, mask_prev);
    sortdecode_kernel<<<NTOK, 256>>>(b_dec, out);
}

// round 5
// speedup vs baseline: 1.3113x; 1.0601x over previous
#include <cuda_runtime.h>
#include <cuda_bf16.h>
#include <cstdint>

// Problem constants
#define IDIM   80
#define HDIM   512
#define WIN    160      // IN_EXTRA + IDIM
#define NSHIFT 81       // IN_EXTRA + 1
#define NTOK   2048     // B*T
#define KSEL   128      // 2*CDIM
#define TPB    8        // tokens per hcompute block

// ---------------- scratch (__device__ globals; no allocation) ----------------
__device__ float g_C[WIN * WIN];            // Gram matrix W_enc^T W_enc (160x160)
__device__ float g_v[WIN];                  // W_enc^T b_enc
__device__ unsigned long long g_packed[NTOK]; // (ordered(E)<<32)|q  via atomicMax
__device__ float g_WeT[WIN * HDIM];         // W_enc transposed
__device__ float g_WdT[HDIM * WIN];         // W_dec transposed
__device__ float g_h[NTOK * HDIM];          // masked h per token

// ---------------- K1: fused prep (gram + transposes + vb + zero) ----------------
// blocks 0..24    : gram 32x32 tile
// blocks 25..104  : transpose W_enc -> g_WeT
// blocks 105..184 : transpose W_dec -> g_WdT
// blocks 185..344 : v[d] = sum_j b_enc[j] * W_enc[j][d]
// block  345      : zero g_packed
__global__ __launch_bounds__(256) void prep_kernel(
    const float* __restrict__ W_enc, const float* __restrict__ b_enc,
    const float* __restrict__ W_dec)
{
    int blk = blockIdx.x;
    int tid = threadIdx.x;

    if (blk < 25) {
        __shared__ float SA[8][32];
        __shared__ float SB[8][32];
        int d0 = (blk % 5) * 32, e0 = (blk / 5) * 32;
        int dd = tid >> 5, ee = tid & 31;
        float a0 = 0.f, a1 = 0.f, a2 = 0.f, a3 = 0.f;
        for (int j0 = 0; j0 < HDIM; j0 += 8) {
            SA[dd][ee] = W_enc[(j0 + dd) * WIN + d0 + ee];
            SB[dd][ee] = W_enc[(j0 + dd) * WIN + e0 + ee];
            __syncthreads();
#pragma unroll
            for (int jj = 0; jj < 8; jj++) {
                float b = SB[jj][ee];
                a0 += SA[jj][dd] * b;
                a1 += SA[jj][dd + 8] * b;
                a2 += SA[jj][dd + 16] * b;
                a3 += SA[jj][dd + 24] * b;
            }
            __syncthreads();
        }
        g_C[(d0 + dd) * WIN + e0 + ee]      = a0;
        g_C[(d0 + dd + 8) * WIN + e0 + ee]  = a1;
        g_C[(d0 + dd + 16) * WIN + e0 + ee] = a2;
        g_C[(d0 + dd + 24) * WIN + e0 + ee] = a3;
    } else if (blk < 105) {
        __shared__ float tile[32][33];
        int bi = blk - 25;
        int bx = (bi % 5) * 32;    // col of W_enc (0..160)
        int by = (bi / 5) * 32;    // row of W_enc (0..512)
        int tx = tid & 31, ty = tid >> 5;
#pragma unroll
        for (int r = 0; r < 4; r++)
            tile[ty + 8 * r][tx] = W_enc[(by + ty + 8 * r) * WIN + bx + tx];
        __syncthreads();
#pragma unroll
        for (int r = 0; r < 4; r++)
            g_WeT[(bx + ty + 8 * r) * HDIM + by + tx] = tile[tx][ty + 8 * r];
    } else if (blk < 185) {
        __shared__ float tile[32][33];
        int bi = blk - 105;
        int bx = (bi / 5) * 32;    // col of W_dec (0..512)
        int by = (bi % 5) * 32;    // row of W_dec (0..160)
        int tx = tid & 31, ty = tid >> 5;
#pragma unroll
        for (int r = 0; r < 4; r++)
            tile[ty + 8 * r][tx] = W_dec[(by + ty + 8 * r) * HDIM + bx + tx];
        __syncthreads();
#pragma unroll
        for (int r = 0; r < 4; r++)
            g_WdT[(bx + ty + 8 * r) * WIN + by + tx] = tile[tx][ty + 8 * r];
    } else if (blk < 345) {
        __shared__ float red[256];
        int d = blk - 185;
        float a = b_enc[tid] * W_enc[tid * WIN + d]
                + b_enc[tid + 256] * W_enc[(tid + 256) * WIN + d];
        red[tid] = a;
        __syncthreads();
        for (int o = 128; o > 0; o >>= 1) {
            if (tid < o) red[tid] += red[tid + o];
            __syncthreads();
        }
        if (tid == 0) g_v[d] = red[0];
    } else {
        for (int i = tid; i < NTOK; i += 256) g_packed[i] = 0ull;
    }
}

// ---------------- K2: energies via Gram quadratic form + fused argmax ----------------
// E(t,s) = x^T C[q:q+80, q:q+80] x + 2 v[q:q+80].x   (const b^T b dropped: argmax-safe)
// atomicMax on packed (ordered(E)<<32)|q : max E wins; tie -> larger q = lower s (jnp.argmax).
#define NS 8
#define CROWS 87
#define CPITCH 96
__global__ __launch_bounds__(128) void energy_kernel(const float* __restrict__ x) {
    __shared__ __align__(16) float Cs[CROWS * CPITCH];
    __shared__ float xs[32 * 81];
    __shared__ float vs[WIN];

    int tid = threadIdx.x;
    int lane = tid & 31;
    int w = tid >> 5;
    int tb = blockIdx.x * 32;
    int s0 = blockIdx.y * NS;
    int qlo = 73 - s0; if (qlo < 0) qlo = 0;

    for (int i = tid; i < CROWS * CPITCH; i += 128) Cs[i] = 0.f;
    for (int i = tid; i < 32 * 81; i += 128) xs[i] = 0.f;
    __syncthreads();
    for (int i = tid; i < CROWS * CROWS; i += 128) {
        int r = i / CROWS, c = i - r * CROWS;
        Cs[r * CPITCH + 4 + c] = g_C[(qlo + r) * WIN + qlo + c];
    }
    for (int i = tid; i < 32 * IDIM; i += 128) {
        int tok = i / IDIM, ii = i - tok * IDIM;
        xs[tok * 81 + ii] = x[(tb + tok) * IDIM + ii];
    }
    for (int i = tid; i < WIN; i += 128) vs[i] = g_v[i];
    __syncthreads();

    const float* myx = &xs[lane * 81];
    float xr[84];
    unsigned long long best = 0ull;

#pragma unroll
    for (int si = 0; si < 2; si++) {
        int s = s0 + w + si * 4;
        if (s > 80) continue;
        int q = 80 - s;
        int coff = q - qlo;           // 0..7
        int p = coff & 3;
        int cbase = 4 + coff - p;     // aligned mod 4

#pragma unroll
        for (int k = 0; k < 84; k++) {
            int i2 = k - p;
            xr[k] = (i2 >= 0 && i2 < IDIM) ? myx[i2] : 0.f;
        }

        float acc = 0.f;
        for (int i = 0; i < IDIM; i++) {
            const float4* cr = reinterpret_cast<const float4*>(&Cs[(coff + i) * CPITCH + cbase]);
            float rd0 = 0.f, rd1 = 0.f;
#pragma unroll
            for (int k4 = 0; k4 < 21; k4++) {
                float4 f = cr[k4];
                if (k4 & 1) {
                    rd1 += f.x * xr[4 * k4] + f.y * xr[4 * k4 + 1]
                         + f.z * xr[4 * k4 + 2] + f.w * xr[4 * k4 + 3];
                } else {
                    rd0 += f.x * xr[4 * k4] + f.y * xr[4 * k4 + 1]
                         + f.z * xr[4 * k4 + 2] + f.w * xr[4 * k4 + 3];
                }
            }
            acc += myx[i] * (rd0 + rd1);
        }
        float cross = 0.f;
        for (int i = 0; i < IDIM; i++) cross += myx[i] * vs[q + i];
        float E = acc + 2.f * cross;

        unsigned eb = __float_as_uint(E);
        unsigned key = eb ^ (unsigned)(((int)eb >> 31) | 0x80000000);
        unsigned long long pk = ((unsigned long long)key << 32) | (unsigned)q;
        if (pk > best) best = pk;
    }
    if (best) atomicMax(&g_packed[tb + lane], best);
}

// ---------------- K3: h for winning shift, 8 tokens/block, coalesced WeT ----------------
__global__ __launch_bounds__(256) void hcompute_kernel(
    const float* __restrict__ x, const float* __restrict__ b_enc,
    const int* __restrict__ mask_prev)
{
    __shared__ float xsp[TPB][WIN];
    __shared__ int qs[TPB];
    int tid = threadIdx.x;
    int tb = blockIdx.x * TPB;

    if (tid < TPB) qs[tid] = (int)(g_packed[tb + tid] & 0xFFFFFFFFull);
    for (int i = tid; i < TPB * WIN; i += 256) ((float*)xsp)[i] = 0.f;
    __syncthreads();
    for (int idx = tid; idx < TPB * IDIM; idx += 256) {
        int t = idx / IDIM, a = idx - t * IDIM;
        xsp[t][qs[t] + a] = x[(tb + t) * IDIM + a];
    }
    __syncthreads();

    int j0 = 2 * tid;
    float a0[TPB], a1[TPB];
#pragma unroll
    for (int t = 0; t < TPB; t++) { a0[t] = 0.f; a1[t] = 0.f; }

    for (int i = 0; i < WIN; i++) {
        float2 c = *reinterpret_cast<const float2*>(&g_WeT[i * HDIM + j0]);
#pragma unroll
        for (int t = 0; t < TPB; t++) {
            float xv = xsp[t][i];
            a0[t] += xv * c.x;
            a1[t] += xv * c.y;
        }
    }

    float bb0 = b_enc[j0], bb1 = b_enc[j0 + 1];
#pragma unroll
    for (int t = 0; t < TPB; t++) {
        int tg = tb + t;
        int2 m = *reinterpret_cast<const int2*>(&mask_prev[tg * HDIM + j0]);
        float h0 = a0[t] + bb0; if (m.x != 0) h0 = 0.f;
        float h1 = a1[t] + bb1; if (m.y != 0) h1 = 0.f;
        *reinterpret_cast<float2*>(&g_h[tg * HDIM + j0]) = make_float2(h0, h1);
    }
}

// ---------------- K4: exact top-128 (bitonic, 1 thread/pair) + sparse decoder ----------------
__global__ __launch_bounds__(256) void sortdecode_kernel(
    const float* __restrict__ b_dec, float* __restrict__ out)
{
    __shared__ unsigned long long keys[HDIM];
    __shared__ float hs[HDIM];
    __shared__ float selv[KSEL];
    __shared__ int   selj[KSEL];
    __shared__ float psum[240];

    int t = blockIdx.x;
    int tid = threadIdx.x;
    int q = (int)(g_packed[t] & 0xFFFFFFFFull);

    {
        float h0 = g_h[t * HDIM + tid];
        float h1 = g_h[t * HDIM + tid + 256];
        hs[tid] = h0;
        hs[tid + 256] = h1;
        keys[tid] = ((unsigned long long)__float_as_uint(h0 * h0) << 32)
                  | (unsigned)(511 - tid);
        keys[tid + 256] = ((unsigned long long)__float_as_uint(h1 * h1) << 32)
                  | (unsigned)(511 - (tid + 256));
    }
    __syncthreads();

    // bitonic sort descending on (bits(h^2), 511-j): exact lax.top_k tie order.
    // one thread per compare pair: idx = 2p - (p & (jj-1)), partner = idx | jj.
    for (int k = 2; k <= HDIM; k <<= 1) {
        for (int jj = k >> 1; jj > 0; jj >>= 1) {
            int idx = 2 * tid - (tid & (jj - 1));
            int ixj = idx | jj;
            unsigned long long a = keys[idx], b2 = keys[ixj];
            bool descBlk = ((idx & k) == 0);
            bool sw = descBlk ? (a < b2) : (a > b2);
            if (sw) { keys[idx] = b2; keys[ixj] = a; }
            __syncthreads();
        }
    }

    if (tid < KSEL) {
        int j = 511 - (int)(keys[tid] & 0xFFFFFFFFull);
        selj[tid] = j;
        selv[tid] = hs[j];
    }
    __syncthreads();

    // sparse decoder: out_i = sum_k selv[k] * WdT[selj[k]][q+i]
    if (tid < 240) {
        int g = tid / IDIM;       // 0..2
        int i = tid - g * IDIM;   // 0..79
        int k0 = (g == 0) ? 0 : (g == 1 ? 43 : 86);
        int k1 = (g == 0) ? 43 : (g == 1 ? 86 : KSEL);
        float a = 0.f;
        for (int k = k0; k < k1; k++)
            a += selv[k] * g_WdT[selj[k] * WIN + q + i];
        psum[tid] = a;
    }
    __syncthreads();
    if (tid < IDIM)
        out[t * IDIM + tid] = psum[tid] + psum[IDIM + tid] + psum[2 * IDIM + tid]
                            + b_dec[q + tid];
}

// ---------------- launch ----------------
extern "C" void kernel_launch(void* const* d_in, const int* in_sizes, int n_in,
                              void* d_out, int out_size) {
    const float* x        = (const float*)d_in[0];
    const float* W_enc    = (const float*)d_in[1];
    const float* b_enc    = (const float*)d_in[2];
    const float* W_dec    = (const float*)d_in[3];
    const float* b_dec    = (const float*)d_in[4];
    const int*   mask_prev= (const int*)d_in[5];
    float* out = (float*)d_out;

    prep_kernel<<<346, 256>>>(W_enc, b_enc, W_dec);
    energy_kernel<<<dim3(64, 11), 128>>>(x);
    hcompute_kernel<<<NTOK / TPB, 256>>>(x, b_enc, mask_prev);
    sortdecode_kernel<<<NTOK, 256>>>(b_dec, out);   // profiled launch (#4)
}

// round 6
// speedup vs baseline: 1.4839x; 1.1317x over previous
#include <cuda_runtime.h>
#include <cuda_bf16.h>
#include <cstdint>

// Problem constants
#define IDIM   80
#define HDIM   512
#define WIN    160      // IN_EXTRA + IDIM
#define NSHIFT 81       // IN_EXTRA + 1
#define NTOK   2048     // B*T
#define KSEL   128      // 2*CDIM
#define TPB    8        // tokens per hcompute block

// ---------------- scratch (__device__ globals; no allocation) ----------------
__device__ float g_C[WIN * WIN];            // Gram matrix W_enc^T W_enc (160x160)
__device__ float g_v[WIN];                  // W_enc^T b_enc
__device__ unsigned long long g_packed[NTOK]; // (ordered(E)<<32)|q  via atomicMax
__device__ float g_WeT[WIN * HDIM];         // W_enc transposed
__device__ float g_WdT[HDIM * WIN];         // W_dec transposed
__device__ float g_h[NTOK * HDIM];          // masked h per token

// ---------------- K1: fused prep (gram + transposes + vb + zero) ----------------
__global__ __launch_bounds__(256) void prep_kernel(
    const float* __restrict__ W_enc, const float* __restrict__ b_enc,
    const float* __restrict__ W_dec)
{
    int blk = blockIdx.x;
    int tid = threadIdx.x;

    if (blk < 25) {
        __shared__ float SA[8][32];
        __shared__ float SB[8][32];
        int d0 = (blk % 5) * 32, e0 = (blk / 5) * 32;
        int dd = tid >> 5, ee = tid & 31;
        float a0 = 0.f, a1 = 0.f, a2 = 0.f, a3 = 0.f;
        for (int j0 = 0; j0 < HDIM; j0 += 8) {
            SA[dd][ee] = W_enc[(j0 + dd) * WIN + d0 + ee];
            SB[dd][ee] = W_enc[(j0 + dd) * WIN + e0 + ee];
            __syncthreads();
#pragma unroll
            for (int jj = 0; jj < 8; jj++) {
                float b = SB[jj][ee];
                a0 += SA[jj][dd] * b;
                a1 += SA[jj][dd + 8] * b;
                a2 += SA[jj][dd + 16] * b;
                a3 += SA[jj][dd + 24] * b;
            }
            __syncthreads();
        }
        g_C[(d0 + dd) * WIN + e0 + ee]      = a0;
        g_C[(d0 + dd + 8) * WIN + e0 + ee]  = a1;
        g_C[(d0 + dd + 16) * WIN + e0 + ee] = a2;
        g_C[(d0 + dd + 24) * WIN + e0 + ee] = a3;
    } else if (blk < 105) {
        __shared__ float tile[32][33];
        int bi = blk - 25;
        int bx = (bi % 5) * 32;    // col of W_enc (0..160)
        int by = (bi / 5) * 32;    // row of W_enc (0..512)
        int tx = tid & 31, ty = tid >> 5;
#pragma unroll
        for (int r = 0; r < 4; r++)
            tile[ty + 8 * r][tx] = W_enc[(by + ty + 8 * r) * WIN + bx + tx];
        __syncthreads();
#pragma unroll
        for (int r = 0; r < 4; r++)
            g_WeT[(bx + ty + 8 * r) * HDIM + by + tx] = tile[tx][ty + 8 * r];
    } else if (blk < 185) {
        __shared__ float tile[32][33];
        int bi = blk - 105;
        int bx = (bi / 5) * 32;    // col of W_dec (0..512)
        int by = (bi % 5) * 32;    // row of W_dec (0..160)
        int tx = tid & 31, ty = tid >> 5;
#pragma unroll
        for (int r = 0; r < 4; r++)
            tile[ty + 8 * r][tx] = W_dec[(by + ty + 8 * r) * HDIM + bx + tx];
        __syncthreads();
#pragma unroll
        for (int r = 0; r < 4; r++)
            g_WdT[(bx + ty + 8 * r) * WIN + by + tx] = tile[tx][ty + 8 * r];
    } else if (blk < 345) {
        __shared__ float red[256];
        int d = blk - 185;
        float a = b_enc[tid] * W_enc[tid * WIN + d]
                + b_enc[tid + 256] * W_enc[(tid + 256) * WIN + d];
        red[tid] = a;
        __syncthreads();
        for (int o = 128; o > 0; o >>= 1) {
            if (tid < o) red[tid] += red[tid + o];
            __syncthreads();
        }
        if (tid == 0) g_v[d] = red[0];
    } else {
        for (int i = tid; i < NTOK; i += 256) g_packed[i] = 0ull;
    }
}

// ---------------- K2: energies via Gram quadratic form + fused argmax ----------------
#define NS 8
#define CROWS 87
#define CPITCH 96
__global__ __launch_bounds__(128) void energy_kernel(const float* __restrict__ x) {
    __shared__ __align__(16) float Cs[CROWS * CPITCH];
    __shared__ float xs[32 * 81];
    __shared__ float vs[WIN];

    int tid = threadIdx.x;
    int lane = tid & 31;
    int w = tid >> 5;
    int tb = blockIdx.x * 32;
    int s0 = blockIdx.y * NS;
    int qlo = 73 - s0; if (qlo < 0) qlo = 0;

    for (int i = tid; i < CROWS * CPITCH; i += 128) Cs[i] = 0.f;
    for (int i = tid; i < 32 * 81; i += 128) xs[i] = 0.f;
    __syncthreads();
    for (int i = tid; i < CROWS * CROWS; i += 128) {
        int r = i / CROWS, c = i - r * CROWS;
        Cs[r * CPITCH + 4 + c] = g_C[(qlo + r) * WIN + qlo + c];
    }
    for (int i = tid; i < 32 * IDIM; i += 128) {
        int tok = i / IDIM, ii = i - tok * IDIM;
        xs[tok * 81 + ii] = x[(tb + tok) * IDIM + ii];
    }
    for (int i = tid; i < WIN; i += 128) vs[i] = g_v[i];
    __syncthreads();

    const float* myx = &xs[lane * 81];
    float xr[84];
    unsigned long long best = 0ull;

#pragma unroll
    for (int si = 0; si < 2; si++) {
        int s = s0 + w + si * 4;
        if (s > 80) continue;
        int q = 80 - s;
        int coff = q - qlo;           // 0..7
        int p = coff & 3;
        int cbase = 4 + coff - p;     // aligned mod 4

#pragma unroll
        for (int k = 0; k < 84; k++) {
            int i2 = k - p;
            xr[k] = (i2 >= 0 && i2 < IDIM) ? myx[i2] : 0.f;
        }

        float acc = 0.f;
        for (int i = 0; i < IDIM; i++) {
            const float4* cr = reinterpret_cast<const float4*>(&Cs[(coff + i) * CPITCH + cbase]);
            float rd0 = 0.f, rd1 = 0.f;
#pragma unroll
            for (int k4 = 0; k4 < 21; k4++) {
                float4 f = cr[k4];
                if (k4 & 1) {
                    rd1 += f.x * xr[4 * k4] + f.y * xr[4 * k4 + 1]
                         + f.z * xr[4 * k4 + 2] + f.w * xr[4 * k4 + 3];
                } else {
                    rd0 += f.x * xr[4 * k4] + f.y * xr[4 * k4 + 1]
                         + f.z * xr[4 * k4 + 2] + f.w * xr[4 * k4 + 3];
                }
            }
            acc += myx[i] * (rd0 + rd1);
        }
        float cross = 0.f;
        for (int i = 0; i < IDIM; i++) cross += myx[i] * vs[q + i];
        float E = acc + 2.f * cross;

        unsigned eb = __float_as_uint(E);
        unsigned key = eb ^ (unsigned)(((int)eb >> 31) | 0x80000000);
        unsigned long long pk = ((unsigned long long)key << 32) | (unsigned)q;
        if (pk > best) best = pk;
    }
    if (best) atomicMax(&g_packed[tb + lane], best);
}

// ---------------- K3: h for winning shift, 8 tokens/block, coalesced WeT ----------------
__global__ __launch_bounds__(256) void hcompute_kernel(
    const float* __restrict__ x, const float* __restrict__ b_enc,
    const int* __restrict__ mask_prev)
{
    __shared__ float xsp[TPB][WIN];
    __shared__ int qs[TPB];
    int tid = threadIdx.x;
    int tb = blockIdx.x * TPB;

    if (tid < TPB) qs[tid] = (int)(g_packed[tb + tid] & 0xFFFFFFFFull);
    for (int i = tid; i < TPB * WIN; i += 256) ((float*)xsp)[i] = 0.f;
    __syncthreads();
    for (int idx = tid; idx < TPB * IDIM; idx += 256) {
        int t = idx / IDIM, a = idx - t * IDIM;
        xsp[t][qs[t] + a] = x[(tb + t) * IDIM + a];
    }
    __syncthreads();

    int j0 = 2 * tid;
    float a0[TPB], a1[TPB];
#pragma unroll
    for (int t = 0; t < TPB; t++) { a0[t] = 0.f; a1[t] = 0.f; }

    for (int i = 0; i < WIN; i++) {
        float2 c = *reinterpret_cast<const float2*>(&g_WeT[i * HDIM + j0]);
#pragma unroll
        for (int t = 0; t < TPB; t++) {
            float xv = xsp[t][i];
            a0[t] += xv * c.x;
            a1[t] += xv * c.y;
        }
    }

    float bb0 = b_enc[j0], bb1 = b_enc[j0 + 1];
#pragma unroll
    for (int t = 0; t < TPB; t++) {
        int tg = tb + t;
        int2 m = *reinterpret_cast<const int2*>(&mask_prev[tg * HDIM + j0]);
        float h0 = a0[t] + bb0; if (m.x != 0) h0 = 0.f;
        float h1 = a1[t] + bb1; if (m.y != 0) h1 = 0.f;
        *reinterpret_cast<float2*>(&g_h[tg * HDIM + j0]) = make_float2(h0, h1);
    }
}

// ---------------- K4: exact top-128 via MSD radix select + sparse decoder ----------------
// Threshold Tv = value bits of the 128th-largest h^2; select {v>Tv} plus the
// (128-gt) lowest-index elements of {v==Tv}  == lax.top_k tie semantics.
// Deterministic: hist/bitmask atomics commute; slots via popc-prefix.
__global__ __launch_bounds__(256) void sortdecode_kernel(
    const float* __restrict__ b_dec, float* __restrict__ out)
{
    __shared__ unsigned vals[HDIM];
    __shared__ float hs[HDIM];
    __shared__ int hist[256];
    __shared__ unsigned selbits[16];
    __shared__ unsigned eqbits[16];
    __shared__ int sPrefix, sR, sGt;
    __shared__ float selv[KSEL];
    __shared__ int   selj[KSEL];
    __shared__ float psum[240];

    int t = blockIdx.x;
    int tid = threadIdx.x;
    int q = (int)(g_packed[t] & 0xFFFFFFFFull);

    float h0 = g_h[t * HDIM + tid];
    float h1 = g_h[t * HDIM + tid + 256];
    hs[tid] = h0;
    hs[tid + 256] = h1;
    unsigned v0 = __float_as_uint(h0 * h0);   // >=0 -> bit-monotonic
    unsigned v1 = __float_as_uint(h1 * h1);
    vals[tid] = v0;
    vals[tid + 256] = v1;
    if (tid == 0) { sPrefix = 0; sR = KSEL; sGt = 0; }
    if (tid < 16) { selbits[tid] = 0u; eqbits[tid] = 0u; }
    __syncthreads();

    // ---- 4-pass MSD radix select (descending) on 32-bit value bits ----
#pragma unroll
    for (int pass = 0; pass < 4; pass++) {
        int shift = 24 - 8 * pass;
        if (tid < 256) hist[tid] = 0;
        __syncthreads();
        int prefix = sPrefix;
        bool act0 = (pass == 0) || ((v0 >> (shift + 8)) == (unsigned)(prefix >> (shift + 8)));
        bool act1 = (pass == 0) || ((v1 >> (shift + 8)) == (unsigned)(prefix >> (shift + 8)));
        if (act0) atomicAdd(&hist[(v0 >> shift) & 255], 1);
        if (act1) atomicAdd(&hist[(v1 >> shift) & 255], 1);
        __syncthreads();
        if (tid < 32) {
            int lane = tid;
            int base = 255 - lane * 8;       // bins base..base-7, descending order
            int c[8], lsum = 0;
#pragma unroll
            for (int i = 0; i < 8; i++) { c[i] = hist[base - i]; lsum += c[i]; }
            int xsc = lsum;
#pragma unroll
            for (int o = 1; o < 32; o <<= 1) {
                int y = __shfl_up_sync(0xffffffffu, xsc, o);
                if (lane >= o) xsc += y;
            }
            int pref = xsc - lsum;           // count in bins strictly above my chunk
            int r = sR;
            if (pref < r && r <= pref + lsum) {
                int run = pref, d = -1, gt_add = 0;
#pragma unroll
                for (int i = 0; i < 8; i++) {
                    if (d < 0 && run + c[i] >= r) { d = base - i; gt_add = run; }
                    run += c[i];
                }
                sPrefix = prefix | (d << shift);
                sR = r - gt_add;
                sGt = sGt + gt_add;
            }
        }
        __syncthreads();
    }

    unsigned Tv = (unsigned)sPrefix;
    int need_eq = KSEL - sGt;

    // ---- selection bitmasks ----
    if (v0 > Tv) atomicOr(&selbits[tid >> 5], 1u << (tid & 31));
    else if (v0 == Tv) atomicOr(&eqbits[tid >> 5], 1u << (tid & 31));
    {
        int j = tid + 256;
        if (v1 > Tv) atomicOr(&selbits[j >> 5], 1u << (j & 31));
        else if (v1 == Tv) atomicOr(&eqbits[j >> 5], 1u << (j & 31));
    }
    __syncthreads();

    // equals: take lowest-index ones until 128 filled
#pragma unroll
    for (int e = 0; e < 2; e++) {
        int j = tid + 256 * e;
        unsigned vv = (e == 0) ? v0 : v1;
        if (vv == Tv) {
            int w = j >> 5;
            int rk = __popc(eqbits[w] & ((1u << (j & 31)) - 1u));
            for (int u = 0; u < w; u++) rk += __popc(eqbits[u]);
            if (rk < need_eq) atomicOr(&selbits[w], 1u << (j & 31));
        }
    }
    __syncthreads();

    // compact: slot = popc-prefix over final mask (deterministic, index-ascending)
#pragma unroll
    for (int e = 0; e < 2; e++) {
        int j = tid + 256 * e;
        int w = j >> 5;
        if (selbits[w] & (1u << (j & 31))) {
            int slot = __popc(selbits[w] & ((1u << (j & 31)) - 1u));
            for (int u = 0; u < w; u++) slot += __popc(selbits[u]);
            selj[slot] = j;
            selv[slot] = hs[j];
        }
    }
    __syncthreads();

    // ---- sparse decoder: out_i = sum_k selv[k] * WdT[selj[k]][q+i] ----
    if (tid < 240) {
        int g = tid / IDIM;       // 0..2
        int i = tid - g * IDIM;   // 0..79
        int k0 = (g == 0) ? 0 : (g == 1 ? 43 : 86);
        int k1 = (g == 0) ? 43 : (g == 1 ? 86 : KSEL);
        float a = 0.f;
        for (int k = k0; k < k1; k++)
            a += selv[k] * g_WdT[selj[k] * WIN + q + i];
        psum[tid] = a;
    }
    __syncthreads();
    if (tid < IDIM)
        out[t * IDIM + tid] = psum[tid] + psum[IDIM + tid] + psum[2 * IDIM + tid]
                            + b_dec[q + tid];
}

// ---------------- launch ----------------
extern "C" void kernel_launch(void* const* d_in, const int* in_sizes, int n_in,
                              void* d_out, int out_size) {
    const float* x        = (const float*)d_in[0];
    const float* W_enc    = (const float*)d_in[1];
    const float* b_enc    = (const float*)d_in[2];
    const float* W_dec    = (const float*)d_in[3];
    const float* b_dec    = (const float*)d_in[4];
    const int*   mask_prev= (const int*)d_in[5];
    float* out = (float*)d_out;

    prep_kernel<<<346, 256>>>(W_enc, b_enc, W_dec);
    energy_kernel<<<dim3(64, 11), 128>>>(x);
    hcompute_kernel<<<NTOK / TPB, 256>>>(x, b_enc, mask_prev);
    sortdecode_kernel<<<NTOK, 256>>>(b_dec, out);   // profiled launch (#4)
}